// round 16
// baseline (speedup 1.0000x reference)
#include <cuda_runtime.h>
#include <cuda_fp16.h>
#include <cstdint>

#define NN 100000
#define NE 1600000
#define DH 64
#define F1 256
#define GEMM_BLOCKS 782          // ceil(100000/128)
#define HIST_BLOCKS 1563         // ceil(400000/256)
#define FC_LDA 72                // A-plane stride (halves)
#define FC_LDB 264               // B-plane stride (halves)

typedef unsigned long long ull;

__device__ __forceinline__ ull pack2(float x) {
    ull r; asm("mov.b64 %0,{%1,%1};" : "=l"(r) : "f"(x)); return r;
}
__device__ __forceinline__ void ffma2(ull& d, ull a, ull b) {
    asm("fma.rn.f32x2 %0,%1,%2,%0;" : "+l"(d) : "l"(a), "l"(b));
}
__device__ __forceinline__ void fadd2(ull& d, ull a) {
    asm("add.rn.f32x2 %0,%0,%1;" : "+l"(d) : "l"(a));
}
__device__ __forceinline__ float2 unpack2(ull v) {
    float2 r; asm("mov.b64 {%0,%1},%2;" : "=f"(r.x), "=f"(r.y) : "l"(v)); return r;
}
__device__ __forceinline__ void mma16816(float* c, const unsigned* a, const unsigned* b) {
    asm volatile("mma.sync.aligned.m16n8k16.row.col.f32.f16.f16.f32 "
        "{%0,%1,%2,%3},{%4,%5,%6,%7},{%8,%9},{%0,%1,%2,%3};"
        : "+f"(c[0]), "+f"(c[1]), "+f"(c[2]), "+f"(c[3])
        : "r"(a[0]), "r"(a[1]), "r"(a[2]), "r"(a[3]), "r"(b[0]), "r"(b[1]));
}
__device__ __forceinline__ void ldsm4(unsigned* r, const void* p) {
    uint32_t a = (uint32_t)__cvta_generic_to_shared(p);
    asm volatile("ldmatrix.sync.aligned.m8n8.x4.shared.b16 {%0,%1,%2,%3},[%4];"
        : "=r"(r[0]), "=r"(r[1]), "=r"(r[2]), "=r"(r[3]) : "r"(a));
}
__device__ __forceinline__ void ldsm2t(unsigned* r, const void* p) {
    uint32_t a = (uint32_t)__cvta_generic_to_shared(p);
    asm volatile("ldmatrix.sync.aligned.m8n8.x2.trans.shared.b16 {%0,%1},[%2];"
        : "=r"(r[0]), "=r"(r[1]) : "r"(a));
}
__device__ __forceinline__ void split2(float x, float y, __half2& hi, __half2& lo) {
    hi = __floats2half2_rn(x, y);
    float2 hf = __half22float2(hi);
    lo = __floats2half2_rn(x - hf.x, y - hf.y);
}

// ---------------- scratch ----------------
__device__ int    g_deg[NN];
__device__ int    g_rowptr[NN + 1];
__device__ int    g_rank[NE];           // per-edge rank within its target bucket
__device__ int    g_srcidx[NE];
__device__ float  g_dinv[NN];
__device__ float  g_h[(NN + 1) * DH];   // +1 dummy ZERO row (index NN) for agg padding;
                                        // zero-initialized, never written -> replay-safe
__device__ float  g_hagg[NN * DH];
__device__ float  g_ssq;

// ---------------- GEMM body: out[n][f] = dinv[n] * sum_k X[n][k]*W[k][f] -----------
__device__ __forceinline__ void gemm_body(const float* __restrict__ X,
                                          const float* __restrict__ W,
                                          float* __restrict__ out, int bid) {
    extern __shared__ float sm[];
    ull*   ws2 = (ull*)sm;         // [64][64] duplicated {w,w}
    float* xs  = sm + 8192;        // [64][130] x transposed
    int tid = threadIdx.x;
    int nb = bid * 128;

    for (int i = tid; i < 4096; i += 256) ws2[i] = pack2(W[i]);

    #pragma unroll
    for (int j = 0; j < 8; j++) {
        int lin = tid + j * 256;
        int n = lin >> 4, k4 = (lin & 15) * 4;
        float4 v = make_float4(0.f, 0.f, 0.f, 0.f);
        if (nb + n < NN) v = *(const float4*)&X[(size_t)(nb + n) * DH + k4];
        xs[(k4 + 0) * 130 + n] = v.x;
        xs[(k4 + 1) * 130 + n] = v.y;
        xs[(k4 + 2) * 130 + n] = v.z;
        xs[(k4 + 3) * 130 + n] = v.w;
    }
    __syncthreads();

    int tx = tid & 15, ty = tid >> 4;
    int n0 = ty * 8;
    ull acc[4][4] = {};
    #pragma unroll 16
    for (int k = 0; k < 64; k++) {
        ull xp[4], wd[4];
        #pragma unroll
        for (int p = 0; p < 4; p++) xp[p] = *(const ull*)&xs[k * 130 + n0 + 2 * p];
        #pragma unroll
        for (int j = 0; j < 4; j++) wd[j] = ws2[k * 64 + tx + 16 * j];
        #pragma unroll
        for (int p = 0; p < 4; p++)
            #pragma unroll
            for (int j = 0; j < 4; j++) ffma2(acc[p][j], xp[p], wd[j]);
    }
    #pragma unroll
    for (int p = 0; p < 4; p++) {
        int n = nb + n0 + 2 * p;
        if (n < NN) {
            bool hi = (n + 1 < NN);
            float slo = g_dinv[n];
            float shi = hi ? g_dinv[n + 1] : 0.f;
            #pragma unroll
            for (int j = 0; j < 4; j++) {
                float2 t = unpack2(acc[p][j]);
                out[(size_t)n * DH + tx + 16 * j] = t.x * slo;
                if (hi) out[(size_t)(n + 1) * DH + tx + 16 * j] = t.y * shi;
            }
        }
    }
}

// ---------------- histogram + rank capture (the ONLY atomic pass) -------------------
__global__ void __launch_bounds__(256) k_hist(const int* __restrict__ ei) {
    int e = blockIdx.x * blockDim.x + threadIdx.x;
    if (e < NE / 4) {
        int4 c = ((const int4*)(ei + NE))[e];
        int4 rk;
        rk.x = atomicAdd(&g_deg[c.x], 1);
        rk.y = atomicAdd(&g_deg[c.y], 1);
        rk.z = atomicAdd(&g_deg[c.z], 1);
        rk.w = atomicAdd(&g_deg[c.w], 1);
        ((int4*)g_rank)[e] = rk;
    }
}

// ---------------- merged scan: rowptr/dinv in ONE kernel ----------------------------
__global__ void __launch_bounds__(1024) k_scan() {
    __shared__ int pred[32];
    __shared__ int wsum[32];
    __shared__ int sbase;
    int tid = threadIdx.x;
    int b = blockIdx.x;
    int lane = tid & 31, w = tid >> 5;

    int pre = 0;
    int nInt4 = b * 256;
    const int4* d4 = (const int4*)g_deg;
    for (int i = tid; i < nInt4; i += 1024) {
        int4 v = d4[i];
        pre += v.x + v.y + v.z + v.w;
    }
    #pragma unroll
    for (int o = 16; o > 0; o >>= 1) pre += __shfl_down_sync(0xffffffffu, pre, o);
    if (lane == 0) pred[w] = pre;
    __syncthreads();
    if (w == 0) {
        int v = pred[lane];
        #pragma unroll
        for (int o = 16; o > 0; o >>= 1) v += __shfl_down_sync(0xffffffffu, v, o);
        if (lane == 0) sbase = v;
    }
    __syncthreads();
    int base = sbase;

    int i = b * 1024 + tid;
    int d = (i < NN) ? g_deg[i] : 0;
    int incl = d;
    #pragma unroll
    for (int o = 1; o < 32; o <<= 1) {
        int t = __shfl_up_sync(0xffffffffu, incl, o);
        if (lane >= o) incl += t;
    }
    if (lane == 31) wsum[w] = incl;
    __syncthreads();
    if (w == 0) {
        int v = wsum[lane];
        #pragma unroll
        for (int o = 1; o < 32; o <<= 1) {
            int t = __shfl_up_sync(0xffffffffu, v, o);
            if (lane >= o) v += t;
        }
        wsum[lane] = v - wsum[lane];
    }
    __syncthreads();
    if (i < NN) {
        int excl = base + wsum[w] + incl - d;
        g_rowptr[i] = excl;
        g_dinv[i] = rsqrtf((float)(d + 1));
        if (i == NN - 1) g_rowptr[NN] = excl + d;
    }
    if (b == 0 && tid == 0) g_ssq = 0.f;
}

// ---------------- fused: scaled gemm1 + ATOMIC-FREE csr scatter ----------------------
__global__ void __launch_bounds__(256) k_csrgemm(const float* __restrict__ X,
                                                 const float* __restrict__ W,
                                                 float* __restrict__ out,
                                                 const int* __restrict__ ei) {
    if (blockIdx.x < GEMM_BLOCKS) {
        gemm_body(X, W, out, blockIdx.x);
    } else {
        int e = (blockIdx.x - GEMM_BLOCKS) * 256 + threadIdx.x;
        if (e < NE / 4) {
            int4 r  = ((const int4*)ei)[e];
            int4 c  = ((const int4*)(ei + NE))[e];
            int4 rk = ((const int4*)g_rank)[e];
            g_srcidx[g_rowptr[c.x] + rk.x] = r.x;
            g_srcidx[g_rowptr[c.y] + rk.y] = r.y;
            g_srcidx[g_rowptr[c.z] + rk.z] = r.z;
            g_srcidx[g_rowptr[c.w] + rk.w] = r.w;
        }
    }
}

__global__ void __launch_bounds__(256) k_gemm(const float* __restrict__ X,
                                              const float* __restrict__ W,
                                              float* __restrict__ out) {
    gemm_body(X, W, out, blockIdx.x);
}

// ---------------- Aggregation: 4 nodes/warp, width-8 shuffles, zero-row padding -----
// hs pre-scaled by dinv (rows 0..NN-1; row NN is all-zero dummy).
// Lane quarter q -> node 4w+q; lane owns 8 features (2x LDG.128).
// Per inner iter: 1 SHFL.w8 + 2 LDG.128 + 4 FADD2 == 4 edges.
__global__ void __launch_bounds__(256) k_agg(const float* __restrict__ hs,
                                             const float* __restrict__ bias,
                                             float* __restrict__ out) {
    int warp = (blockIdx.x * blockDim.x + threadIdx.x) >> 5;
    int lane = threadIdx.x & 31;
    if (warp >= NN / 4) return;
    int q  = lane >> 3;
    int l8 = lane & 7;
    int n = warp * 4 + q;

    const ulonglong2* hp = (const ulonglong2*)hs;   // 16B units; row = 16 units
    size_t rbase = (size_t)n * 16 + l8 * 2;
    ulonglong2 sv0 = hp[rbase];
    ulonglong2 sv1 = hp[rbase + 1];
    ull a0 = sv0.x, a1 = sv0.y, a2 = sv1.x, a3 = sv1.y;

    int beg = g_rowptr[n], end = g_rowptr[n + 1];
    int deg = end - beg;
    int m = max(deg, __shfl_xor_sync(0xffffffffu, deg, 8));
    m = max(m, __shfl_xor_sync(0xffffffffu, m, 16));

    for (int j = 0; j < m; j += 8) {
        int k = j + l8;
        int s = (k < deg) ? g_srcidx[beg + k] : NN;   // dummy zero row when exhausted
        int mrem = min(8, m - j);
        #pragma unroll 4
        for (int t = 0; t < mrem; t++) {
            int ss = __shfl_sync(0xffffffffu, s, t, 8);   // width-8: per-quarter bcast
            size_t sb = (size_t)ss * 16 + l8 * 2;
            ulonglong2 v0 = hp[sb];
            ulonglong2 v1 = hp[sb + 1];
            fadd2(a0, v0.x); fadd2(a1, v0.y);
            fadd2(a2, v1.x); fadd2(a3, v1.y);
        }
    }

    float dn = g_dinv[n];
    int f0 = l8 * 8;
    float4 bb0 = *(const float4*)&bias[f0];
    float4 bb1 = *(const float4*)&bias[f0 + 4];
    float2 p0 = unpack2(a0), p1 = unpack2(a1), p2 = unpack2(a2), p3 = unpack2(a3);
    float4 o0, o1;
    o0.x = fmaxf(fmaf(p0.x, dn, bb0.x), 0.f);
    o0.y = fmaxf(fmaf(p0.y, dn, bb0.y), 0.f);
    o0.z = fmaxf(fmaf(p1.x, dn, bb0.z), 0.f);
    o0.w = fmaxf(fmaf(p1.y, dn, bb0.w), 0.f);
    o1.x = fmaxf(fmaf(p2.x, dn, bb1.x), 0.f);
    o1.y = fmaxf(fmaf(p2.y, dn, bb1.y), 0.f);
    o1.z = fmaxf(fmaf(p3.x, dn, bb1.z), 0.f);
    o1.w = fmaxf(fmaf(p3.y, dn, bb1.w), 0.f);
    *(float4*)&out[(size_t)n * DH + f0]     = o0;
    *(float4*)&out[(size_t)n * DH + f0 + 4] = o1;
}

// ---------------- MLP head: split-fp16 3-pass HMMA, fp32-exact -----------------------
__global__ void __launch_bounds__(256) k_fcmma(const float* __restrict__ H,
                                               const float* __restrict__ W1f,
                                               const float* __restrict__ b1f,
                                               const float* __restrict__ w2,
                                               const float* __restrict__ b2,
                                               float* __restrict__ out) {
    extern __shared__ char smc[];
    __half* Bhi = (__half*)smc;                                    // [64][FC_LDB]
    __half* Blo = Bhi + 64 * FC_LDB;
    __half* Ahi = Blo + 64 * FC_LDB;                               // [128][FC_LDA]
    __half* Alo = Ahi + 128 * FC_LDA;
    float*  b1s = (float*)(Alo + 128 * FC_LDA);
    float*  w2s = b1s + F1;
    float*  sred = w2s + F1;                                       // [8]

    int tid = threadIdx.x;
    int nb = blockIdx.x * 128;

    const float2* Wv = (const float2*)W1f;
    #pragma unroll
    for (int j = 0; j < 32; j++) {
        int f2 = tid + j * 256;          // 8192 float2
        int k = f2 >> 7, n = (f2 & 127) * 2;
        float2 v = Wv[f2];
        __half2 hi, lo; split2(v.x, v.y, hi, lo);
        *(__half2*)&Bhi[k * FC_LDB + n] = hi;
        *(__half2*)&Blo[k * FC_LDB + n] = lo;
    }
    b1s[tid] = b1f[tid];
    w2s[tid] = w2[tid];

    #pragma unroll
    for (int j = 0; j < 8; j++) {
        int t = tid + j * 256;           // 2048 float4
        int r = t >> 4, c4 = (t & 15) * 4;
        float4 v = make_float4(0.f, 0.f, 0.f, 0.f);
        if (nb + r < NN) v = *(const float4*)&H[(size_t)(nb + r) * DH + c4];
        __half2 hi0, lo0, hi1, lo1;
        split2(v.x, v.y, hi0, lo0);
        split2(v.z, v.w, hi1, lo1);
        *(__half2*)&Ahi[r * FC_LDA + c4]     = hi0;
        *(__half2*)&Ahi[r * FC_LDA + c4 + 2] = hi1;
        *(__half2*)&Alo[r * FC_LDA + c4]     = lo0;
        *(__half2*)&Alo[r * FC_LDA + c4 + 2] = lo1;
    }
    __syncthreads();

    int lane = tid & 31, w = tid >> 5;
    int row0 = w * 16;

    unsigned ahi[4][4], alo[4][4];
    #pragma unroll
    for (int ks = 0; ks < 4; ks++) {
        int off = (row0 + (lane & 15)) * FC_LDA + (lane >> 4) * 8 + ks * 16;
        ldsm4(ahi[ks], &Ahi[off]);
        ldsm4(alo[ks], &Alo[off]);
    }

    float b2v = b2[0];
    float s0 = 0.f, s1 = 0.f;
    #pragma unroll
    for (int n8 = 0; n8 < 32; n8++) {
        int n0 = n8 * 8;
        float c[4] = {0.f, 0.f, 0.f, 0.f};
        #pragma unroll
        for (int ks = 0; ks < 4; ks++) {
            int roff = ((lane & 15) + ks * 16) * FC_LDB + n0;
            unsigned bh[2], bl[2];
            ldsm2t(bh, &Bhi[roff]);
            ldsm2t(bl, &Blo[roff]);
            mma16816(c, ahi[ks], bh);
            mma16816(c, alo[ks], bh);
            mma16816(c, ahi[ks], bl);
        }
        int col = n0 + (lane & 3) * 2;
        float2 bb = *(const float2*)&b1s[col];
        float2 ww = *(const float2*)&w2s[col];
        s0 += fmaxf(c[0] + bb.x, 0.f) * ww.x + fmaxf(c[1] + bb.y, 0.f) * ww.y;
        s1 += fmaxf(c[2] + bb.x, 0.f) * ww.x + fmaxf(c[3] + bb.y, 0.f) * ww.y;
    }
    s0 += __shfl_xor_sync(0xffffffffu, s0, 1);
    s0 += __shfl_xor_sync(0xffffffffu, s0, 2);
    s1 += __shfl_xor_sync(0xffffffffu, s1, 1);
    s1 += __shfl_xor_sync(0xffffffffu, s1, 2);

    float lsq = 0.f;
    if ((lane & 3) == 0) {
        int n = nb + row0 + (lane >> 2);
        float o0 = s0 + b2v, o1 = s1 + b2v;
        if (n < NN)     { out[n] = o0;     lsq += o0 * o0; }
        if (n + 8 < NN) { out[n + 8] = o1; lsq += o1 * o1; }
    }
    #pragma unroll
    for (int o = 16; o > 0; o >>= 1) lsq += __shfl_down_sync(0xffffffffu, lsq, o);
    if (lane == 0) sred[w] = lsq;
    __syncthreads();
    if (tid == 0) {
        float t = 0.f;
        #pragma unroll
        for (int q = 0; q < 8; q++) t += sred[q];
        atomicAdd(&g_ssq, t);
    }
}

__global__ void k_norm(float* __restrict__ out) {
    float s = 1.f / fmaxf(sqrtf(g_ssq), 1e-12f);
    int i = blockIdx.x * blockDim.x + threadIdx.x;
    if (i < NN) out[i] *= s;
}

// ---------------- launcher ----------------
extern "C" void kernel_launch(void* const* d_in, const int* in_sizes, int n_in,
                              void* d_out, int out_size) {
    const float* x    = (const float*)d_in[0];
    const int*   ei   = (const int*)d_in[1];
    const float* W1   = (const float*)d_in[2];
    const float* b1   = (const float*)d_in[3];
    const float* W2   = (const float*)d_in[4];
    const float* b2   = (const float*)d_in[5];
    const float* fc1w = (const float*)d_in[6];
    const float* fc1b = (const float*)d_in[7];
    const float* fc2w = (const float*)d_in[8];
    const float* fc2b = (const float*)d_in[9];
    float* out = (float*)d_out;

    void *p_h = nullptr, *p_hagg = nullptr, *p_deg = nullptr;
    cudaGetSymbolAddress(&p_h, g_h);
    cudaGetSymbolAddress(&p_hagg, g_hagg);
    cudaGetSymbolAddress(&p_deg, g_deg);
    float* h    = (float*)p_h;
    float* hagg = (float*)p_hagg;

    const int SMEM = 8192 * 4 + 64 * 130 * 4;   // 66048 (gemm)
    const int SMEM_FC = 2 * 64 * FC_LDB * 2 + 2 * 128 * FC_LDA * 2 + 2 * F1 * 4 + 32;
    cudaFuncSetAttribute(k_csrgemm, cudaFuncAttributeMaxDynamicSharedMemorySize, SMEM);
    cudaFuncSetAttribute(k_gemm,    cudaFuncAttributeMaxDynamicSharedMemorySize, SMEM);
    cudaFuncSetAttribute(k_fcmma,   cudaFuncAttributeMaxDynamicSharedMemorySize, SMEM_FC);

    cudaMemsetAsync(p_deg, 0, NN * sizeof(int));

    k_hist<<<HIST_BLOCKS, 256>>>(ei);
    k_scan<<<98, 1024>>>();
    k_csrgemm<<<GEMM_BLOCKS + HIST_BLOCKS, 256, SMEM>>>(x, W1, h, ei);

    const int agg_blocks = (NN / 4 + 7) / 8;   // 3125 (4 nodes per warp)

    k_agg<<<agg_blocks, 256>>>(h, b1, hagg);
    k_gemm<<<GEMM_BLOCKS, 256, SMEM>>>(hagg, W2, h);
    k_agg<<<agg_blocks, 256>>>(h, b2, hagg);
    k_fcmma<<<GEMM_BLOCKS, 256, SMEM_FC>>>(hagg, fc1w, fc1b, fc2w, fc2b, out);
    k_norm<<<(NN + 255) / 256, 256>>>(out);
}

// round 17
// speedup vs baseline: 1.1393x; 1.1393x over previous
#include <cuda_runtime.h>
#include <cuda_fp16.h>
#include <cstdint>

#define NN 100000
#define NE 1600000
#define DH 64
#define F1 256
#define GEMM_BLOCKS 782          // ceil(100000/128)
#define HIST_BLOCKS 1563         // ceil(400000/256)
#define WCVT_BLOCKS 32           // fc1w fp32 -> hi/lo fp16 conversion (8192 float2)
#define FC_LDA 72                // A-plane stride (halves)
#define FC_LDB 264               // B-plane stride (halves)

typedef unsigned long long ull;

__device__ __forceinline__ ull pack2(float x) {
    ull r; asm("mov.b64 %0,{%1,%1};" : "=l"(r) : "f"(x)); return r;
}
__device__ __forceinline__ void ffma2(ull& d, ull a, ull b) {
    asm("fma.rn.f32x2 %0,%1,%2,%0;" : "+l"(d) : "l"(a), "l"(b));
}
__device__ __forceinline__ void fadd2(ull& d, ull a) {
    asm("add.rn.f32x2 %0,%0,%1;" : "+l"(d) : "l"(a));
}
__device__ __forceinline__ float2 unpack2(ull v) {
    float2 r; asm("mov.b64 {%0,%1},%2;" : "=f"(r.x), "=f"(r.y) : "l"(v)); return r;
}
__device__ __forceinline__ void mma16816(float* c, const unsigned* a, const unsigned* b) {
    asm volatile("mma.sync.aligned.m16n8k16.row.col.f32.f16.f16.f32 "
        "{%0,%1,%2,%3},{%4,%5,%6,%7},{%8,%9},{%0,%1,%2,%3};"
        : "+f"(c[0]), "+f"(c[1]), "+f"(c[2]), "+f"(c[3])
        : "r"(a[0]), "r"(a[1]), "r"(a[2]), "r"(a[3]), "r"(b[0]), "r"(b[1]));
}
__device__ __forceinline__ void ldsm4(unsigned* r, const void* p) {
    uint32_t a = (uint32_t)__cvta_generic_to_shared(p);
    asm volatile("ldmatrix.sync.aligned.m8n8.x4.shared.b16 {%0,%1,%2,%3},[%4];"
        : "=r"(r[0]), "=r"(r[1]), "=r"(r[2]), "=r"(r[3]) : "r"(a));
}
__device__ __forceinline__ void ldsm2t(unsigned* r, const void* p) {
    uint32_t a = (uint32_t)__cvta_generic_to_shared(p);
    asm volatile("ldmatrix.sync.aligned.m8n8.x2.trans.shared.b16 {%0,%1},[%2];"
        : "=r"(r[0]), "=r"(r[1]) : "r"(a));
}
__device__ __forceinline__ void split2(float x, float y, __half2& hi, __half2& lo) {
    hi = __floats2half2_rn(x, y);
    float2 hf = __half22float2(hi);
    lo = __floats2half2_rn(x - hf.x, y - hf.y);
}

// ---------------- scratch ----------------
__device__ int    g_deg[NN];
__device__ int    g_rowptr[NN + 1];
__device__ int    g_rank[NE];           // per-edge rank within its target bucket
__device__ int    g_srcidx[NE];
__device__ float  g_dinv[NN];
__device__ float  g_h[(NN + 1) * DH];   // +1 dummy ZERO row (index NN) for agg padding
__device__ float  g_hagg[NN * DH];
__device__ __half g_w1hi[64 * F1];      // fc1w hi plane (precomputed)
__device__ __half g_w1lo[64 * F1];      // fc1w lo plane (precomputed)
__device__ float  g_ssq;

// ---------------- GEMM body: out[n][f] = dinv[n] * sum_k X[n][k]*W[k][f] -----------
__device__ __forceinline__ void gemm_body(const float* __restrict__ X,
                                          const float* __restrict__ W,
                                          float* __restrict__ out, int bid) {
    extern __shared__ float sm[];
    ull*   ws2 = (ull*)sm;         // [64][64] duplicated {w,w}
    float* xs  = sm + 8192;        // [64][130] x transposed
    int tid = threadIdx.x;
    int nb = bid * 128;

    for (int i = tid; i < 4096; i += 256) ws2[i] = pack2(W[i]);

    #pragma unroll
    for (int j = 0; j < 8; j++) {
        int lin = tid + j * 256;
        int n = lin >> 4, k4 = (lin & 15) * 4;
        float4 v = make_float4(0.f, 0.f, 0.f, 0.f);
        if (nb + n < NN) v = *(const float4*)&X[(size_t)(nb + n) * DH + k4];
        xs[(k4 + 0) * 130 + n] = v.x;
        xs[(k4 + 1) * 130 + n] = v.y;
        xs[(k4 + 2) * 130 + n] = v.z;
        xs[(k4 + 3) * 130 + n] = v.w;
    }
    __syncthreads();

    int tx = tid & 15, ty = tid >> 4;
    int n0 = ty * 8;
    ull acc[4][4] = {};
    #pragma unroll 16
    for (int k = 0; k < 64; k++) {
        ull xp[4], wd[4];
        #pragma unroll
        for (int p = 0; p < 4; p++) xp[p] = *(const ull*)&xs[k * 130 + n0 + 2 * p];
        #pragma unroll
        for (int j = 0; j < 4; j++) wd[j] = ws2[k * 64 + tx + 16 * j];
        #pragma unroll
        for (int p = 0; p < 4; p++)
            #pragma unroll
            for (int j = 0; j < 4; j++) ffma2(acc[p][j], xp[p], wd[j]);
    }
    #pragma unroll
    for (int p = 0; p < 4; p++) {
        int n = nb + n0 + 2 * p;
        if (n < NN) {
            bool hi = (n + 1 < NN);
            float slo = g_dinv[n];
            float shi = hi ? g_dinv[n + 1] : 0.f;
            #pragma unroll
            for (int j = 0; j < 4; j++) {
                float2 t = unpack2(acc[p][j]);
                out[(size_t)n * DH + tx + 16 * j] = t.x * slo;
                if (hi) out[(size_t)(n + 1) * DH + tx + 16 * j] = t.y * shi;
            }
        }
    }
}

// ---------------- fused: histogram+rank (atomics) + fc1w split precompute -----------
__global__ void __launch_bounds__(256) k_hist(const int* __restrict__ ei,
                                              const float* __restrict__ W1f) {
    if (blockIdx.x < HIST_BLOCKS) {
        int e = blockIdx.x * 256 + threadIdx.x;
        if (e < NE / 4) {
            int4 c = ((const int4*)(ei + NE))[e];
            int4 rk;
            rk.x = atomicAdd(&g_deg[c.x], 1);
            rk.y = atomicAdd(&g_deg[c.y], 1);
            rk.z = atomicAdd(&g_deg[c.z], 1);
            rk.w = atomicAdd(&g_deg[c.w], 1);
            ((int4*)g_rank)[e] = rk;
        }
    } else {
        // fc1w (64x256 fp32) -> hi/lo fp16 planes, once, in hist's shadow
        int f2 = (blockIdx.x - HIST_BLOCKS) * 256 + threadIdx.x;   // 8192 float2
        float2 v = ((const float2*)W1f)[f2];
        __half2 hi, lo; split2(v.x, v.y, hi, lo);
        ((__half2*)g_w1hi)[f2] = hi;
        ((__half2*)g_w1lo)[f2] = lo;
    }
}

// ---------------- merged scan: rowptr/dinv in ONE kernel ----------------------------
__global__ void __launch_bounds__(1024) k_scan() {
    __shared__ int pred[32];
    __shared__ int wsum[32];
    __shared__ int sbase;
    int tid = threadIdx.x;
    int b = blockIdx.x;
    int lane = tid & 31, w = tid >> 5;

    int pre = 0;
    int nInt4 = b * 256;
    const int4* d4 = (const int4*)g_deg;
    for (int i = tid; i < nInt4; i += 1024) {
        int4 v = d4[i];
        pre += v.x + v.y + v.z + v.w;
    }
    #pragma unroll
    for (int o = 16; o > 0; o >>= 1) pre += __shfl_down_sync(0xffffffffu, pre, o);
    if (lane == 0) pred[w] = pre;
    __syncthreads();
    if (w == 0) {
        int v = pred[lane];
        #pragma unroll
        for (int o = 16; o > 0; o >>= 1) v += __shfl_down_sync(0xffffffffu, v, o);
        if (lane == 0) sbase = v;
    }
    __syncthreads();
    int base = sbase;

    int i = b * 1024 + tid;
    int d = (i < NN) ? g_deg[i] : 0;
    int incl = d;
    #pragma unroll
    for (int o = 1; o < 32; o <<= 1) {
        int t = __shfl_up_sync(0xffffffffu, incl, o);
        if (lane >= o) incl += t;
    }
    if (lane == 31) wsum[w] = incl;
    __syncthreads();
    if (w == 0) {
        int v = wsum[lane];
        #pragma unroll
        for (int o = 1; o < 32; o <<= 1) {
            int t = __shfl_up_sync(0xffffffffu, v, o);
            if (lane >= o) v += t;
        }
        wsum[lane] = v - wsum[lane];
    }
    __syncthreads();
    if (i < NN) {
        int excl = base + wsum[w] + incl - d;
        g_rowptr[i] = excl;
        g_dinv[i] = rsqrtf((float)(d + 1));
        if (i == NN - 1) g_rowptr[NN] = excl + d;
    }
    if (b == 0 && tid == 0) g_ssq = 0.f;
}

// ---------------- fused: scaled gemm1 + ATOMIC-FREE csr scatter ----------------------
__global__ void __launch_bounds__(256) k_csrgemm(const float* __restrict__ X,
                                                 const float* __restrict__ W,
                                                 float* __restrict__ out,
                                                 const int* __restrict__ ei) {
    if (blockIdx.x < GEMM_BLOCKS) {
        gemm_body(X, W, out, blockIdx.x);
    } else {
        int e = (blockIdx.x - GEMM_BLOCKS) * 256 + threadIdx.x;
        if (e < NE / 4) {
            int4 r  = ((const int4*)ei)[e];
            int4 c  = ((const int4*)(ei + NE))[e];
            int4 rk = ((const int4*)g_rank)[e];
            g_srcidx[g_rowptr[c.x] + rk.x] = r.x;
            g_srcidx[g_rowptr[c.y] + rk.y] = r.y;
            g_srcidx[g_rowptr[c.z] + rk.z] = r.z;
            g_srcidx[g_rowptr[c.w] + rk.w] = r.w;
        }
    }
}

__global__ void __launch_bounds__(256) k_gemm(const float* __restrict__ X,
                                              const float* __restrict__ W,
                                              float* __restrict__ out) {
    gemm_body(X, W, out, blockIdx.x);
}

// ---------------- Aggregation (R15 proven): 2 nodes/warp, width-16 shuffles ---------
__global__ void __launch_bounds__(256) k_agg(const float* __restrict__ hs,
                                             const float* __restrict__ bias,
                                             float* __restrict__ out) {
    int warp = (blockIdx.x * blockDim.x + threadIdx.x) >> 5;
    int lane = threadIdx.x & 31;
    if (warp >= NN / 2) return;
    int half = lane >> 4;
    int l16  = lane & 15;
    int n = warp * 2 + half;

    const ulonglong2* hp = (const ulonglong2*)hs;   // 16B units; row = 16 units
    ulonglong2 self = hp[(size_t)n * 16 + l16];
    ull acc0 = self.x, acc1 = self.y;

    int beg = g_rowptr[n], end = g_rowptr[n + 1];
    int deg = end - beg;
    int odeg = __shfl_xor_sync(0xffffffffu, deg, 16);
    int mdeg = max(deg, odeg);

    for (int j = 0; j < mdeg; j += 16) {
        int k = j + l16;
        int s = (k < deg) ? g_srcidx[beg + k] : NN;   // dummy zero row when exhausted
        int mrem = min(16, mdeg - j);
        #pragma unroll 4
        for (int t = 0; t < mrem; t++) {
            int ss = __shfl_sync(0xffffffffu, s, t, 16);   // width-16: per-half bcast
            ulonglong2 v = hp[(size_t)ss * 16 + l16];
            fadd2(acc0, v.x);
            fadd2(acc1, v.y);
        }
    }

    float dn = g_dinv[n];
    int f0 = l16 * 4;
    float4 bb = *(const float4*)&bias[f0];
    float2 a0 = unpack2(acc0), a1 = unpack2(acc1);
    float4 o;
    o.x = fmaxf(fmaf(a0.x, dn, bb.x), 0.f);
    o.y = fmaxf(fmaf(a0.y, dn, bb.y), 0.f);
    o.z = fmaxf(fmaf(a1.x, dn, bb.z), 0.f);
    o.w = fmaxf(fmaf(a1.y, dn, bb.w), 0.f);
    *(float4*)&out[(size_t)n * DH + f0] = o;
}

// ---------------- MLP head: split-fp16 3-pass HMMA, fp32-exact -----------------------
// B planes precomputed in g_w1hi/lo -> staging is plain uint4 copies.
__global__ void __launch_bounds__(256) k_fcmma(const float* __restrict__ H,
                                               const float* __restrict__ b1f,
                                               const float* __restrict__ w2,
                                               const float* __restrict__ b2,
                                               float* __restrict__ out) {
    extern __shared__ char smc[];
    __half* Bhi = (__half*)smc;                                    // [64][FC_LDB]
    __half* Blo = Bhi + 64 * FC_LDB;
    __half* Ahi = Blo + 64 * FC_LDB;                               // [128][FC_LDA]
    __half* Alo = Ahi + 128 * FC_LDA;
    float*  b1s = (float*)(Alo + 128 * FC_LDA);
    float*  w2s = b1s + F1;
    float*  sred = w2s + F1;                                       // [8]

    int tid = threadIdx.x;
    int nb = blockIdx.x * 128;

    // stage precomputed B planes: 2048 uint4 per plane, 8 per thread
    #pragma unroll
    for (int j = 0; j < 8; j++) {
        int t = tid + j * 256;           // uint4 index; r = t/32, c8 = (t%32)*8
        int r = t >> 5, c8 = (t & 31) * 8;
        *(uint4*)&Bhi[r * FC_LDB + c8] = *(const uint4*)&g_w1hi[r * F1 + c8];
        *(uint4*)&Blo[r * FC_LDB + c8] = *(const uint4*)&g_w1lo[r * F1 + c8];
    }
    b1s[tid] = b1f[tid];
    w2s[tid] = w2[tid];

    #pragma unroll
    for (int j = 0; j < 8; j++) {
        int t = tid + j * 256;           // 2048 float4
        int r = t >> 4, c4 = (t & 15) * 4;
        float4 v = make_float4(0.f, 0.f, 0.f, 0.f);
        if (nb + r < NN) v = *(const float4*)&H[(size_t)(nb + r) * DH + c4];
        __half2 hi0, lo0, hi1, lo1;
        split2(v.x, v.y, hi0, lo0);
        split2(v.z, v.w, hi1, lo1);
        *(__half2*)&Ahi[r * FC_LDA + c4]     = hi0;
        *(__half2*)&Ahi[r * FC_LDA + c4 + 2] = hi1;
        *(__half2*)&Alo[r * FC_LDA + c4]     = lo0;
        *(__half2*)&Alo[r * FC_LDA + c4 + 2] = lo1;
    }
    __syncthreads();

    int lane = tid & 31, w = tid >> 5;
    int row0 = w * 16;

    unsigned ahi[4][4], alo[4][4];
    #pragma unroll
    for (int ks = 0; ks < 4; ks++) {
        int off = (row0 + (lane & 15)) * FC_LDA + (lane >> 4) * 8 + ks * 16;
        ldsm4(ahi[ks], &Ahi[off]);
        ldsm4(alo[ks], &Alo[off]);
    }

    float b2v = b2[0];
    float s0 = 0.f, s1 = 0.f;
    #pragma unroll
    for (int n8 = 0; n8 < 32; n8++) {
        int n0 = n8 * 8;
        float c[4] = {0.f, 0.f, 0.f, 0.f};
        #pragma unroll
        for (int ks = 0; ks < 4; ks++) {
            int roff = ((lane & 15) + ks * 16) * FC_LDB + n0;
            unsigned bh[2], bl[2];
            ldsm2t(bh, &Bhi[roff]);
            ldsm2t(bl, &Blo[roff]);
            mma16816(c, ahi[ks], bh);
            mma16816(c, alo[ks], bh);
            mma16816(c, ahi[ks], bl);
        }
        int col = n0 + (lane & 3) * 2;
        float2 bb = *(const float2*)&b1s[col];
        float2 ww = *(const float2*)&w2s[col];
        s0 += fmaxf(c[0] + bb.x, 0.f) * ww.x + fmaxf(c[1] + bb.y, 0.f) * ww.y;
        s1 += fmaxf(c[2] + bb.x, 0.f) * ww.x + fmaxf(c[3] + bb.y, 0.f) * ww.y;
    }
    s0 += __shfl_xor_sync(0xffffffffu, s0, 1);
    s0 += __shfl_xor_sync(0xffffffffu, s0, 2);
    s1 += __shfl_xor_sync(0xffffffffu, s1, 1);
    s1 += __shfl_xor_sync(0xffffffffu, s1, 2);

    float lsq = 0.f;
    if ((lane & 3) == 0) {
        int n = nb + row0 + (lane >> 2);
        float o0 = s0 + b2v, o1 = s1 + b2v;
        if (n < NN)     { out[n] = o0;     lsq += o0 * o0; }
        if (n + 8 < NN) { out[n + 8] = o1; lsq += o1 * o1; }
    }
    #pragma unroll
    for (int o = 16; o > 0; o >>= 1) lsq += __shfl_down_sync(0xffffffffu, lsq, o);
    if (lane == 0) sred[w] = lsq;
    __syncthreads();
    if (tid == 0) {
        float t = 0.f;
        #pragma unroll
        for (int q = 0; q < 8; q++) t += sred[q];
        atomicAdd(&g_ssq, t);
    }
}

__global__ void k_norm(float* __restrict__ out) {
    float s = 1.f / fmaxf(sqrtf(g_ssq), 1e-12f);
    int i = blockIdx.x * blockDim.x + threadIdx.x;
    if (i < NN) out[i] *= s;
}

// ---------------- launcher ----------------
extern "C" void kernel_launch(void* const* d_in, const int* in_sizes, int n_in,
                              void* d_out, int out_size) {
    const float* x    = (const float*)d_in[0];
    const int*   ei   = (const int*)d_in[1];
    const float* W1   = (const float*)d_in[2];
    const float* b1   = (const float*)d_in[3];
    const float* W2   = (const float*)d_in[4];
    const float* b2   = (const float*)d_in[5];
    const float* fc1w = (const float*)d_in[6];
    const float* fc1b = (const float*)d_in[7];
    const float* fc2w = (const float*)d_in[8];
    const float* fc2b = (const float*)d_in[9];
    float* out = (float*)d_out;

    void *p_h = nullptr, *p_hagg = nullptr, *p_deg = nullptr;
    cudaGetSymbolAddress(&p_h, g_h);
    cudaGetSymbolAddress(&p_hagg, g_hagg);
    cudaGetSymbolAddress(&p_deg, g_deg);
    float* h    = (float*)p_h;
    float* hagg = (float*)p_hagg;

    const int SMEM = 8192 * 4 + 64 * 130 * 4;   // 66048 (gemm)
    const int SMEM_FC = 2 * 64 * FC_LDB * 2 + 2 * 128 * FC_LDA * 2 + 2 * F1 * 4 + 32;
    cudaFuncSetAttribute(k_csrgemm, cudaFuncAttributeMaxDynamicSharedMemorySize, SMEM);
    cudaFuncSetAttribute(k_gemm,    cudaFuncAttributeMaxDynamicSharedMemorySize, SMEM);
    cudaFuncSetAttribute(k_fcmma,   cudaFuncAttributeMaxDynamicSharedMemorySize, SMEM_FC);

    cudaMemsetAsync(p_deg, 0, NN * sizeof(int));

    k_hist<<<HIST_BLOCKS + WCVT_BLOCKS, 256>>>(ei, fc1w);   // atomics+rank || W split
    k_scan<<<98, 1024>>>();
    k_csrgemm<<<GEMM_BLOCKS + HIST_BLOCKS, 256, SMEM>>>(x, W1, h, ei);

    const int agg_blocks = (NN / 2 + 7) / 8;   // 6250 (2 nodes per warp)

    k_agg<<<agg_blocks, 256>>>(h, b1, hagg);
    k_gemm<<<GEMM_BLOCKS, 256, SMEM>>>(hagg, W2, h);
    k_agg<<<agg_blocks, 256>>>(h, b2, hagg);
    k_fcmma<<<GEMM_BLOCKS, 256, SMEM_FC>>>(hagg, fc1b, fc2w, fc2b, out);
    k_norm<<<(NN + 255) / 256, 256>>>(out);
}